// round 1
// baseline (speedup 1.0000x reference)
#include <cuda_runtime.h>

// Problem constants
#define TOKS   32768      // B*L = 16*2048
#define DIMD   128        // D
#define KCB    8192       // codebook size
#define TM     128        // tokens per CTA
#define TN     128        // codes per chunk
#define NCHUNK (KCB / TN) // 64
#define NTHREADS 256

// smem: xs[128k][128tok] + cs[128k][128code] + cns[128]
#define SMEM_FLOATS (TM*DIMD + TN*DIMD + TN)
#define SMEM_BYTES  (SMEM_FLOATS * 4)

__device__ float g_cnorm[KCB];

// ||c||^2 per code
__global__ void cnorm_kernel(const float* __restrict__ cb) {
    int code = blockIdx.x * blockDim.x + threadIdx.x;
    if (code >= KCB) return;
    const float4* p = (const float4*)(cb + (size_t)code * DIMD);
    float s = 0.f;
#pragma unroll
    for (int i = 0; i < DIMD / 4; ++i) {
        float4 v = p[i];
        s = fmaf(v.x, v.x, s);
        s = fmaf(v.y, v.y, s);
        s = fmaf(v.z, v.z, s);
        s = fmaf(v.w, v.w, s);
    }
    g_cnorm[code] = s;
}

// Main VQ kernel: per CTA, 128 tokens vs all 8192 codes.
// d2(token, code) = ||c||^2 - 2*dot(x,c)   (||x||^2 dropped: constant per token)
__global__ __launch_bounds__(NTHREADS, 1) void vq_kernel(
    const float* __restrict__ ze, const float* __restrict__ cb,
    float* __restrict__ out, int out_size)
{
    extern __shared__ float sm[];
    float* xs  = sm;                  // [k][token], 128*128
    float* cs  = sm + TM * DIMD;      // [k][code],  128*128
    float* cns = cs + TN * DIMD;      // [128]

    const int t  = threadIdx.x;
    const int tx = t & 15;            // code-group id (16)
    const int ty = t >> 4;            // token-group id (16)
    const int tok0 = blockIdx.x * TM;

    const float4* zev = (const float4*)ze;
    const float4* cbv = (const float4*)cb;

    // ---- load x tile, transposed to [k][token] ----
#pragma unroll
    for (int i = 0; i < 16; ++i) {
        int f  = t * 16 + i;          // 0..4095 float4s
        int tl = f >> 5;              // local token (32 float4 per row)
        int k4 = f & 31;
        float4 v = zev[(size_t)(tok0 + tl) * 32 + k4];
        xs[(4 * k4 + 0) * TM + tl] = v.x;
        xs[(4 * k4 + 1) * TM + tl] = v.y;
        xs[(4 * k4 + 2) * TM + tl] = v.z;
        xs[(4 * k4 + 3) * TM + tl] = v.w;
    }

    // Per-thread running argmin over 8 token rows:
    // token rows: ty*4 + {0..3}  and  64 + ty*4 + {0..3}
    float best[8];
    int   bidx[8];
#pragma unroll
    for (int i = 0; i < 8; ++i) { best[i] = 3.4e38f; bidx[i] = 0; }

    for (int ch = 0; ch < NCHUNK; ++ch) {
        __syncthreads();              // previous chunk reads of cs done
        const int code0 = ch * TN;
        // ---- load code chunk, transposed to [k][code] ----
#pragma unroll
        for (int i = 0; i < 16; ++i) {
            int f  = t * 16 + i;
            int cl = f >> 5;
            int k4 = f & 31;
            float4 v = cbv[(size_t)(code0 + cl) * 32 + k4];
            cs[(4 * k4 + 0) * TN + cl] = v.x;
            cs[(4 * k4 + 1) * TN + cl] = v.y;
            cs[(4 * k4 + 2) * TN + cl] = v.z;
            cs[(4 * k4 + 3) * TN + cl] = v.w;
        }
        if (t < TN) cns[t] = g_cnorm[code0 + t];
        __syncthreads();

        float acc[8][8];
#pragma unroll
        for (int i = 0; i < 8; ++i)
#pragma unroll
            for (int j = 0; j < 8; ++j) acc[i][j] = 0.f;

        // ---- 8x8 register outer product over K=128 ----
#pragma unroll 4
        for (int kk = 0; kk < DIMD; ++kk) {
            float4 xa  = *(const float4*)&xs[kk * TM + ty * 4];
            float4 xb  = *(const float4*)&xs[kk * TM + 64 + ty * 4];
            float4 ca  = *(const float4*)&cs[kk * TN + tx * 4];
            float4 cb2 = *(const float4*)&cs[kk * TN + 64 + tx * 4];
            float xr[8] = {xa.x, xa.y, xa.z, xa.w, xb.x, xb.y, xb.z, xb.w};
            float cr[8] = {ca.x, ca.y, ca.z, ca.w, cb2.x, cb2.y, cb2.z, cb2.w};
#pragma unroll
            for (int i = 0; i < 8; ++i)
#pragma unroll
                for (int j = 0; j < 8; ++j)
                    acc[i][j] = fmaf(xr[i], cr[j], acc[i][j]);
        }

        // ---- fold into running argmin ----
#pragma unroll
        for (int j = 0; j < 8; ++j) {
            int colj = (j < 4) ? (tx * 4 + j) : (64 + tx * 4 + (j - 4));
            float cn = cns[colj];
            int code = code0 + colj;
#pragma unroll
            for (int i = 0; i < 8; ++i) {
                float d2 = fmaf(-2.f, acc[i][j], cn);
                if (d2 < best[i]) { best[i] = d2; bidx[i] = code; }
            }
        }
    }

    // ---- cross-thread (over tx) argmin reduction via smem (reuse xs region) ----
    __syncthreads();
    float* rv   = sm;                         // [128][16]
    int*   ri   = (int*)(sm + TM * 16);       // [128][16]
    int*   sidx = (int*)(sm + TM * 16 * 2);   // [128]
#pragma unroll
    for (int i = 0; i < 8; ++i) {
        int row = (i < 4) ? (ty * 4 + i) : (64 + ty * 4 + (i - 4));
        rv[row * 16 + tx] = best[i];
        ri[row * 16 + tx] = bidx[i];
    }
    __syncthreads();
    if (t < TM) {
        float bv = rv[t * 16 + 0];
        int   bi = ri[t * 16 + 0];
#pragma unroll
        for (int j = 1; j < 16; ++j) {
            float v = rv[t * 16 + j];
            if (v < bv) { bv = v; bi = ri[t * 16 + j]; }
        }
        sidx[t] = bi;
        // indices output (as float values), after the z_q block — if present
        if (out_size > TOKS * DIMD)
            out[(size_t)TOKS * DIMD + tok0 + t] = (float)bi;
    }
    __syncthreads();

    // ---- gather z_q = codebook[idx] ----
    float4* outv = (float4*)out;
#pragma unroll
    for (int i = 0; i < 16; ++i) {
        int f  = i * NTHREADS + t;
        int tl = f >> 5;
        int k4 = f & 31;
        outv[(size_t)(tok0 + tl) * 32 + k4] = cbv[(size_t)sidx[tl] * 32 + k4];
    }
}

extern "C" void kernel_launch(void* const* d_in, const int* in_sizes, int n_in,
                              void* d_out, int out_size) {
    const float* ze = (const float*)d_in[0];
    const float* cb = (const float*)d_in[1];
    // Defensive: auto-detect ordering by element counts (sizes are distinct).
    if (n_in >= 2 && in_sizes[0] == KCB * DIMD && in_sizes[1] == TOKS * DIMD) {
        const float* tmp = ze; ze = cb; cb = tmp;
    }

    cudaFuncSetAttribute(vq_kernel, cudaFuncAttributeMaxDynamicSharedMemorySize,
                         SMEM_BYTES);

    cnorm_kernel<<<(KCB + 255) / 256, 256>>>(cb);
    vq_kernel<<<TOKS / TM, NTHREADS, SMEM_BYTES>>>(ze, cb, (float*)d_out, out_size);
}

// round 2
// speedup vs baseline: 1.1715x; 1.1715x over previous
#include <cuda_runtime.h>

// Problem constants
#define TOKS   32768      // B*L
#define DIMD   128        // D
#define KCB    8192       // codebook size
#define TM     128        // tokens per CTA tile
#define TN     256        // codes per smem chunk
#define NQ     4          // codebook quarters (for wave balance)
#define QCODES (KCB / NQ) // 2048 codes per CTA
#define NCHUNK (QCODES / TN) // 8
#define NTILES (TOKS / TM)   // 256
#define NTHREADS 256

// smem: xs[128k][128tok] + cs[128k][256code] + cns[256]
#define SMEM_FLOATS (TM*DIMD + TN*DIMD + TN)
#define SMEM_BYTES  (SMEM_FLOATS * 4)

__device__ float g_cnorm[KCB];
__device__ float g_bestd[NQ * TOKS];
__device__ int   g_besti[NQ * TOKS];

// ---- packed fp32x2 helpers (Blackwell FFMA2) ----
__device__ __forceinline__ void ffma2(unsigned long long& d,
                                      unsigned long long a,
                                      unsigned long long b) {
    asm("fma.rn.f32x2 %0, %1, %2, %0;" : "+l"(d) : "l"(a), "l"(b));
}
__device__ __forceinline__ unsigned long long pack2(float lo, float hi) {
    unsigned long long r;
    asm("mov.b64 %0, {%1, %2};" : "=l"(r) : "f"(lo), "f"(hi));
    return r;
}
__device__ __forceinline__ void unpack2(unsigned long long v, float& lo, float& hi) {
    asm("mov.b64 {%0, %1}, %2;" : "=f"(lo), "=f"(hi) : "l"(v));
}

// ||c||^2 per code
__global__ void cnorm_kernel(const float* __restrict__ cb) {
    int code = blockIdx.x * blockDim.x + threadIdx.x;
    if (code >= KCB) return;
    const float4* p = (const float4*)(cb + (size_t)code * DIMD);
    float s = 0.f;
#pragma unroll
    for (int i = 0; i < DIMD / 4; ++i) {
        float4 v = p[i];
        s = fmaf(v.x, v.x, s);
        s = fmaf(v.y, v.y, s);
        s = fmaf(v.z, v.z, s);
        s = fmaf(v.w, v.w, s);
    }
    g_cnorm[code] = s;
}

// Main VQ kernel: CTA = (token tile of 128) x (codebook quarter of 2048).
// d2(token, code) = ||c||^2 - 2*dot(x,c)   (||x||^2 dropped: constant per token)
__global__ __launch_bounds__(NTHREADS, 1) void vq_kernel(
    const float* __restrict__ ze, const float* __restrict__ cb)
{
    extern __shared__ float sm[];
    float* xs  = sm;                  // [k][token], 128*128
    float* cs  = sm + TM * DIMD;      // [k][code],  128*256
    float* cns = cs + TN * DIMD;      // [256]

    const int b    = blockIdx.x;
    const int tile = b >> 2;
    const int q    = b & 3;
    const int tok0 = tile * TM;
    const int cbase = q * QCODES;

    const int t  = threadIdx.x;
    const int tx = t & 15;            // code-group id (16 groups)
    const int ty = t >> 4;            // token-group id (16 groups, 8 tokens each)

    const float4* zev = (const float4*)ze;
    const float4* cbv = (const float4*)cb;

    // ---- load x tile, transposed to [k][token] ----
#pragma unroll
    for (int i = 0; i < 16; ++i) {
        int f  = t * 16 + i;          // 0..4095 float4s
        int tl = f >> 5;              // local token (32 float4 per row)
        int k4 = f & 31;
        float4 v = zev[(size_t)(tok0 + tl) * 32 + k4];
        xs[(4 * k4 + 0) * TM + tl] = v.x;
        xs[(4 * k4 + 1) * TM + tl] = v.y;
        xs[(4 * k4 + 2) * TM + tl] = v.z;
        xs[(4 * k4 + 3) * TM + tl] = v.w;
    }

    // Per-thread running argmin over 8 token rows (tokens ty*8 .. ty*8+7)
    float best[8];
    int   bidx[8];
#pragma unroll
    for (int i = 0; i < 8; ++i) { best[i] = 3.4e38f; bidx[i] = 0; }

    for (int ch = 0; ch < NCHUNK; ++ch) {
        __syncthreads();              // previous chunk reads of cs done
        const int code0 = cbase + ch * TN;
        // ---- load code chunk, transposed to [k][code] ----
        // thread t loads code row (code0 + t); STS is conflict-free
        {
            const float4* crow = cbv + (size_t)(code0 + t) * 32;
#pragma unroll
            for (int i = 0; i < 32; ++i) {
                float4 v = crow[i];
                cs[(4 * i + 0) * TN + t] = v.x;
                cs[(4 * i + 1) * TN + t] = v.y;
                cs[(4 * i + 2) * TN + t] = v.z;
                cs[(4 * i + 3) * TN + t] = v.w;
            }
        }
        cns[t] = g_cnorm[code0 + t];
        __syncthreads();

        // acc[i][jc]: token (ty*8+i) vs packed code pair jc
        // code pair jc -> local codes (g*64 + tx*4 + 2p) + {0,1}, g=jc>>1, p=jc&1
        unsigned long long acc[8][8];
#pragma unroll
        for (int i = 0; i < 8; ++i)
#pragma unroll
            for (int j = 0; j < 8; ++j) acc[i][j] = 0ULL;

#pragma unroll 4
        for (int kk = 0; kk < DIMD; ++kk) {
            // x fragment: 8 consecutive tokens (broadcast across tx)
            float4 xa = *(const float4*)&xs[kk * TM + ty * 8];
            float4 xb = *(const float4*)&xs[kk * TM + ty * 8 + 4];
            unsigned long long xp[8];
            xp[0] = pack2(xa.x, xa.x); xp[1] = pack2(xa.y, xa.y);
            xp[2] = pack2(xa.z, xa.z); xp[3] = pack2(xa.w, xa.w);
            xp[4] = pack2(xb.x, xb.x); xp[5] = pack2(xb.y, xb.y);
            xp[6] = pack2(xb.z, xb.z); xp[7] = pack2(xb.w, xb.w);
            // c fragment: 4 groups, each a contiguous 16B (2 packed pairs)
            unsigned long long cp[8];
#pragma unroll
            for (int g = 0; g < 4; ++g) {
                ulonglong2 cc = *(const ulonglong2*)&cs[kk * TN + g * 64 + tx * 4];
                cp[g * 2 + 0] = cc.x;
                cp[g * 2 + 1] = cc.y;
            }
#pragma unroll
            for (int i = 0; i < 8; ++i)
#pragma unroll
                for (int j = 0; j < 8; ++j)
                    ffma2(acc[i][j], xp[i], cp[j]);
        }

        // ---- fold into running argmin ----
#pragma unroll
        for (int jc = 0; jc < 8; ++jc) {
            int g = jc >> 1, p = jc & 1;
            int cl = g * 64 + tx * 4 + 2 * p;     // local code (low of pair)
            float cn0 = cns[cl], cn1 = cns[cl + 1];
            int c0 = code0 + cl;
#pragma unroll
            for (int i = 0; i < 8; ++i) {
                float da, db;
                unpack2(acc[i][jc], da, db);
                float d2a = fmaf(-2.f, da, cn0);
                float d2b = fmaf(-2.f, db, cn1);
                if (d2a < best[i]) { best[i] = d2a; bidx[i] = c0; }
                if (d2b < best[i]) { best[i] = d2b; bidx[i] = c0 + 1; }
            }
        }
    }

    // ---- cross-thread (over tx) argmin reduction via smem (reuse xs) ----
    __syncthreads();
    float* rv = sm;                         // [128][16]
    int*   ri = (int*)(sm + TM * 16);       // [128][16]
#pragma unroll
    for (int i = 0; i < 8; ++i) {
        int row = ty * 8 + i;
        rv[row * 16 + tx] = best[i];
        ri[row * 16 + tx] = bidx[i];
    }
    __syncthreads();
    if (t < TM) {
        float bv = rv[t * 16 + 0];
        int   bi = ri[t * 16 + 0];
#pragma unroll
        for (int j = 1; j < 16; ++j) {
            float v = rv[t * 16 + j];
            if (v < bv) { bv = v; bi = ri[t * 16 + j]; }
        }
        g_bestd[q * TOKS + tok0 + t] = bv;
        g_besti[q * TOKS + tok0 + t] = bi;
    }
}

// Merge quarters, write indices, gather z_q = codebook[idx]
__global__ __launch_bounds__(256) void merge_gather_kernel(
    const float* __restrict__ cb, float* __restrict__ out, int out_size)
{
    __shared__ int sidx[64];
    const int t = threadIdx.x;
    const int tokBase = blockIdx.x * 64;

    if (t < 64) {
        int tok = tokBase + t;
        float bv = g_bestd[tok];
        int   bi = g_besti[tok];
#pragma unroll
        for (int qq = 1; qq < NQ; ++qq) {
            float v = g_bestd[qq * TOKS + tok];
            if (v < bv) { bv = v; bi = g_besti[qq * TOKS + tok]; }
        }
        sidx[t] = bi;
        if (out_size > TOKS * DIMD)
            out[(size_t)TOKS * DIMD + tok] = (float)bi;
    }
    __syncthreads();

    float4* outv = (float4*)out;
    const float4* cbv = (const float4*)cb;
#pragma unroll
    for (int i = 0; i < 8; ++i) {
        int f    = i * 256 + t;       // 0..2047 float4s (64 tokens x 32)
        int tl   = f >> 5;
        int lane = f & 31;
        outv[(size_t)(tokBase + tl) * 32 + lane] =
            cbv[(size_t)sidx[tl] * 32 + lane];
    }
}

extern "C" void kernel_launch(void* const* d_in, const int* in_sizes, int n_in,
                              void* d_out, int out_size) {
    const float* ze = (const float*)d_in[0];
    const float* cb = (const float*)d_in[1];
    // Defensive: auto-detect ordering by element counts (sizes are distinct).
    if (n_in >= 2 && in_sizes[0] == KCB * DIMD && in_sizes[1] == TOKS * DIMD) {
        const float* tmp = ze; ze = cb; cb = tmp;
    }

    cudaFuncSetAttribute(vq_kernel, cudaFuncAttributeMaxDynamicSharedMemorySize,
                         SMEM_BYTES);

    cnorm_kernel<<<(KCB + 255) / 256, 256>>>(cb);
    vq_kernel<<<NTILES * NQ, NTHREADS, SMEM_BYTES>>>(ze, cb);
    merge_gather_kernel<<<TOKS / 64, 256>>>(cb, (float*)d_out, out_size);
}

// round 4
// speedup vs baseline: 1.5541x; 1.3266x over previous
#include <cuda_runtime.h>
#include <cstdint>

// ---------------- problem constants ----------------
#define TOKS   32768
#define DIMD   128
#define KCB    8192
#define TM     128              // tokens per CTA
#define NQ     4                // codebook quarters
#define QCODES (KCB / NQ)       // 2048
#define CHUNK  128              // codes per B chunk
#define NCHUNK (QCODES / CHUNK) // 16
#define NTILES (TOKS / TM)      // 256
#define LDA    132              // padded row stride (floats) -> conflict-free
#define A_FLOATS (TM * LDA)     // 16896
#define B_FLOATS (CHUNK * LDA)  // 16896
#define SMEM_FLOATS (A_FLOATS + 2 * B_FLOATS)
#define SMEM_BYTES  (SMEM_FLOATS * 4)   // 202752

__device__ float g_cnorm[KCB];
__device__ float g_bestd[NQ * TOKS];
__device__ int   g_besti[NQ * TOKS];

// ---------------- PTX helpers (all baseline sm_80+, no 'a' features) ----------------
__device__ __forceinline__ uint32_t tf32_of(float x) {
    uint32_t r;
    asm("cvt.rna.tf32.f32 %0, %1;" : "=r"(r) : "f"(x));
    return r;
}
__device__ __forceinline__ void split_tf32(float x, uint32_t& hi, uint32_t& lo) {
    hi = tf32_of(x);
    lo = tf32_of(x - __uint_as_float(hi));
}
__device__ __forceinline__ void cp_async16(uint32_t saddr, const void* gptr) {
    asm volatile("cp.async.cg.shared.global [%0], [%1], 16;"
                 :: "r"(saddr), "l"(gptr) : "memory");
}
#define CP_COMMIT() asm volatile("cp.async.commit_group;" ::: "memory")
#define CP_WAIT1()  asm volatile("cp.async.wait_group 1;" ::: "memory")
#define CP_WAIT0()  asm volatile("cp.async.wait_group 0;" ::: "memory")

// m16n8k8 tf32 MMA, D += A*B (fp32 accumulate)
__device__ __forceinline__ void mma_tf32(float* d, const uint32_t* a,
                                         const uint32_t* b) {
    asm volatile(
        "mma.sync.aligned.m16n8k8.row.col.f32.tf32.tf32.f32 "
        "{%0,%1,%2,%3}, {%4,%5,%6,%7}, {%8,%9}, {%0,%1,%2,%3};"
        : "+f"(d[0]), "+f"(d[1]), "+f"(d[2]), "+f"(d[3])
        : "r"(a[0]), "r"(a[1]), "r"(a[2]), "r"(a[3]), "r"(b[0]), "r"(b[1]));
}

// ---------------- prep: ||c||^2 (one warp per code row) ----------------
__global__ __launch_bounds__(256) void prep_kernel(const float* __restrict__ cb) {
    int w = (blockIdx.x * blockDim.x + threadIdx.x) >> 5;
    int l = threadIdx.x & 31;
    if (w >= KCB) return;
    float4 v = ((const float4*)cb)[(size_t)w * 32 + l];
    float s = v.x * v.x + v.y * v.y + v.z * v.z + v.w * v.w;
#pragma unroll
    for (int o = 16; o; o >>= 1) s += __shfl_xor_sync(0xffffffffu, s, o);
    if (l == 0) g_cnorm[w] = s;
}

// ---------------- main VQ kernel (split-tf32 3-pass mma.sync) ----------------
__global__ __launch_bounds__(256, 1) void vq_kernel(
    const float* __restrict__ ze, const float* __restrict__ cb)
{
    extern __shared__ float sm[];
    float* As = sm;                  // [token][k], pad LDA
    float* Bs = sm + A_FLOATS;       // 2 stages [code][k], pad LDA

    const int t      = threadIdx.x;
    const int lane   = t & 31;
    const int wid    = t >> 5;
    const int g      = lane >> 2;    // groupID (0..7)
    const int tg     = lane & 3;     // thread-in-group
    const int warp_m = wid >> 2;     // 0..1 (64 tokens each)
    const int warp_n = wid & 3;      // 0..3 (32 codes each)

    const int tile  = blockIdx.x >> 2;
    const int q     = blockIdx.x & 3;
    const int tok0  = tile * TM;
    const int cbase = q * QCODES;

    // ---- load A = -2 * z_e tile into smem ----
#pragma unroll
    for (int i = 0; i < 16; ++i) {
        int f   = t + i * 256;
        int row = f >> 5, k4 = f & 31;
        float4 v = ((const float4*)ze)[(size_t)(tok0 + row) * 32 + k4];
        v.x *= -2.f; v.y *= -2.f; v.z *= -2.f; v.w *= -2.f;
        *(float4*)&As[row * LDA + k4 * 4] = v;
    }

    // ---- prefetch chunk 0 ----
    {
        uint32_t bb = (uint32_t)__cvta_generic_to_shared(Bs);
        const int code0 = cbase;
#pragma unroll
        for (int i = 0; i < 16; ++i) {
            int f   = t + i * 256;
            int row = f >> 5, k4 = f & 31;
            cp_async16(bb + (uint32_t)(row * LDA + k4 * 4) * 4,
                       cb + (size_t)(code0 + row) * DIMD + k4 * 4);
        }
        CP_COMMIT();
    }

    float best[8];
    int   bidx[8];
#pragma unroll
    for (int s = 0; s < 8; ++s) { best[s] = 3.4e38f; bidx[s] = 0; }

    for (int ch = 0; ch < NCHUNK; ++ch) {
        if (ch + 1 < NCHUNK) {
            uint32_t bb = (uint32_t)__cvta_generic_to_shared(
                Bs + ((ch + 1) & 1) * B_FLOATS);
            const int code0 = cbase + (ch + 1) * CHUNK;
#pragma unroll
            for (int i = 0; i < 16; ++i) {
                int f   = t + i * 256;
                int row = f >> 5, k4 = f & 31;
                cp_async16(bb + (uint32_t)(row * LDA + k4 * 4) * 4,
                           cb + (size_t)(code0 + row) * DIMD + k4 * 4);
            }
            CP_COMMIT();
            CP_WAIT1();
        } else {
            CP_WAIT0();
        }
        __syncthreads();   // chunk ch resident for all warps

        const float* bs = Bs + (ch & 1) * B_FLOATS;

        float acc[4][4][4];
#pragma unroll
        for (int mt = 0; mt < 4; ++mt)
#pragma unroll
            for (int nt = 0; nt < 4; ++nt)
#pragma unroll
                for (int r = 0; r < 4; ++r) acc[mt][nt][r] = 0.f;

#pragma unroll 4
        for (int ks = 0; ks < 16; ++ks) {
            const int k0 = ks * 8;
            // A fragments (raw fp32 -> hi/lo tf32)
            uint32_t ahi[4][4], alo[4][4];
#pragma unroll
            for (int mt = 0; mt < 4; ++mt) {
                int r0 = warp_m * 64 + mt * 16 + g;
                float a0 = As[r0 * LDA + k0 + tg];
                float a1 = As[(r0 + 8) * LDA + k0 + tg];
                float a2 = As[r0 * LDA + k0 + tg + 4];
                float a3 = As[(r0 + 8) * LDA + k0 + tg + 4];
                split_tf32(a0, ahi[mt][0], alo[mt][0]);
                split_tf32(a1, ahi[mt][1], alo[mt][1]);
                split_tf32(a2, ahi[mt][2], alo[mt][2]);
                split_tf32(a3, ahi[mt][3], alo[mt][3]);
            }
            // B fragments
            uint32_t bhi[4][2], blo[4][2];
#pragma unroll
            for (int nt = 0; nt < 4; ++nt) {
                int c0 = warp_n * 32 + nt * 8 + g;
                float b0 = bs[c0 * LDA + k0 + tg];
                float b1 = bs[c0 * LDA + k0 + tg + 4];
                split_tf32(b0, bhi[nt][0], blo[nt][0]);
                split_tf32(b1, bhi[nt][1], blo[nt][1]);
            }
            // 3-pass split-tf32 MMAs
#pragma unroll
            for (int mt = 0; mt < 4; ++mt)
#pragma unroll
                for (int nt = 0; nt < 4; ++nt) {
                    mma_tf32(acc[mt][nt], ahi[mt], bhi[nt]);
                    mma_tf32(acc[mt][nt], ahi[mt], blo[nt]);
                    mma_tf32(acc[mt][nt], alo[mt], bhi[nt]);
                }
        }

        // ---- fold chunk into running argmin ----
        const int code0 = cbase + ch * CHUNK;
#pragma unroll
        for (int nt = 0; nt < 4; ++nt) {
            int cl = code0 + warp_n * 32 + nt * 8 + 2 * tg;
            float cn0 = __ldg(&g_cnorm[cl]);
            float cn1 = __ldg(&g_cnorm[cl + 1]);
#pragma unroll
            for (int mt = 0; mt < 4; ++mt) {
                float d0 = acc[mt][nt][0] + cn0;
                float d1 = acc[mt][nt][1] + cn1;
                float d2 = acc[mt][nt][2] + cn0;
                float d3 = acc[mt][nt][3] + cn1;
                int s0 = mt * 2, s1 = mt * 2 + 1;
                if (d0 < best[s0]) { best[s0] = d0; bidx[s0] = cl; }
                if (d1 < best[s0]) { best[s0] = d1; bidx[s0] = cl + 1; }
                if (d2 < best[s1]) { best[s1] = d2; bidx[s1] = cl; }
                if (d3 < best[s1]) { best[s1] = d3; bidx[s1] = cl + 1; }
            }
        }
        __syncthreads();   // all warps done reading stage (ch&1) before overwrite
    }

    // ---- reduce: lanes (tg) -> smem -> per-token ----
    float* rv = sm;                       // [128][4]
    int*   ri = (int*)(sm + 512);         // [128][4]
#pragma unroll
    for (int s = 0; s < 8; ++s) {
        float b = best[s];
        int   bi = bidx[s];
#pragma unroll
        for (int off = 1; off < 4; off <<= 1) {
            float ob = __shfl_xor_sync(0xffffffffu, b, off);
            int   oi = __shfl_xor_sync(0xffffffffu, bi, off);
            if (ob < b || (ob == b && oi < bi)) { b = ob; bi = oi; }
        }
        if (tg == 0) {
            int row = warp_m * 64 + (s >> 1) * 16 + g + 8 * (s & 1);
            rv[row * 4 + warp_n] = b;
            ri[row * 4 + warp_n] = bi;
        }
    }
    __syncthreads();
    if (t < TM) {
        float bv = rv[t * 4 + 0];
        int   bi = ri[t * 4 + 0];
#pragma unroll
        for (int j = 1; j < 4; ++j) {
            float v = rv[t * 4 + j];
            int   i2 = ri[t * 4 + j];
            if (v < bv || (v == bv && i2 < bi)) { bv = v; bi = i2; }
        }
        g_bestd[q * TOKS + tok0 + t] = bv;
        g_besti[q * TOKS + tok0 + t] = bi;
    }
}

// ---------------- merge quarters, write indices, gather z_q ----------------
__global__ __launch_bounds__(256) void merge_gather_kernel(
    const float* __restrict__ cb, float* __restrict__ out, int out_size)
{
    __shared__ int sidx[64];
    const int t = threadIdx.x;
    const int tokBase = blockIdx.x * 64;

    if (t < 64) {
        int tok = tokBase + t;
        float bv = g_bestd[tok];
        int   bi = g_besti[tok];
#pragma unroll
        for (int qq = 1; qq < NQ; ++qq) {
            float v = g_bestd[qq * TOKS + tok];
            int   i2 = g_besti[qq * TOKS + tok];
            if (v < bv || (v == bv && i2 < bi)) { bv = v; bi = i2; }
        }
        sidx[t] = bi;
        if (out_size > TOKS * DIMD)
            out[(size_t)TOKS * DIMD + tok] = (float)bi;
    }
    __syncthreads();

    float4* outv = (float4*)out;
    const float4* cbv = (const float4*)cb;
#pragma unroll
    for (int i = 0; i < 8; ++i) {
        int f    = i * 256 + t;
        int tl   = f >> 5;
        int lanE = f & 31;
        outv[(size_t)(tokBase + tl) * 32 + lanE] =
            cbv[(size_t)sidx[tl] * 32 + lanE];
    }
}

extern "C" void kernel_launch(void* const* d_in, const int* in_sizes, int n_in,
                              void* d_out, int out_size) {
    const float* ze = (const float*)d_in[0];
    const float* cb = (const float*)d_in[1];
    if (n_in >= 2 && in_sizes[0] == KCB * DIMD && in_sizes[1] == TOKS * DIMD) {
        const float* tmp = ze; ze = cb; cb = tmp;
    }

    cudaFuncSetAttribute(vq_kernel, cudaFuncAttributeMaxDynamicSharedMemorySize,
                         SMEM_BYTES);

    prep_kernel<<<KCB / 8, 256>>>(cb);
    vq_kernel<<<NTILES * NQ, 256, SMEM_BYTES>>>(ze, cb);
    merge_gather_kernel<<<TOKS / 64, 256>>>(cb, (float*)d_out, out_size);
}

// round 5
// speedup vs baseline: 1.7586x; 1.1316x over previous
#include <cuda_runtime.h>
#include <cstdint>

// ---------------- problem constants ----------------
#define TOKS   32768
#define DIMD   128
#define KCB    8192
#define TM     128              // tokens per CTA
#define NQ     4                // codebook quarters
#define QCODES (KCB / NQ)       // 2048
#define CHUNK  128              // codes per B chunk
#define NCHUNK (QCODES / CHUNK) // 16
#define NTILES (TOKS / TM)      // 256
#define LDA    132              // padded row stride (floats)
#define A_FLOATS (TM * LDA)
#define B_FLOATS (CHUNK * LDA)
#define SMEM_FLOATS (A_FLOATS + 2 * B_FLOATS)
#define SMEM_BYTES  (SMEM_FLOATS * 4)   // 202752
#define TAU    0.1f             // screening rescore margin

__device__ float g_cnorm[KCB];
__device__ float g_cb_tf[KCB * DIMD];       // tf32-rounded codebook
__device__ float g_bestd[NQ * TOKS * 3];    // per-quarter top-3 screened d2
__device__ int   g_besti[NQ * TOKS * 3];

// ---------------- PTX helpers (baseline sm_80+ only) ----------------
__device__ __forceinline__ float tf32r(float x) {
    uint32_t r;
    asm("cvt.rna.tf32.f32 %0, %1;" : "=r"(r) : "f"(x));
    return __uint_as_float(r);
}
__device__ __forceinline__ void cp_async16(uint32_t saddr, const void* gptr) {
    asm volatile("cp.async.cg.shared.global [%0], [%1], 16;"
                 :: "r"(saddr), "l"(gptr) : "memory");
}
#define CP_COMMIT() asm volatile("cp.async.commit_group;" ::: "memory")
#define CP_WAIT1()  asm volatile("cp.async.wait_group 1;" ::: "memory")
#define CP_WAIT0()  asm volatile("cp.async.wait_group 0;" ::: "memory")

__device__ __forceinline__ void mma_tf32(float* d, const uint32_t* a,
                                         const uint32_t* b) {
    asm volatile(
        "mma.sync.aligned.m16n8k8.row.col.f32.tf32.tf32.f32 "
        "{%0,%1,%2,%3}, {%4,%5,%6,%7}, {%8,%9}, {%0,%1,%2,%3};"
        : "+f"(d[0]), "+f"(d[1]), "+f"(d[2]), "+f"(d[3])
        : "r"(a[0]), "r"(a[1]), "r"(a[2]), "r"(a[3]), "r"(b[0]), "r"(b[1]));
}

// insert candidate into sorted top-3 (strict < keeps earlier/smaller idx on tie)
__device__ __forceinline__ void ins3(float d, int c, float* b, int* bi) {
    if (d < b[2]) {
        if (d < b[1]) {
            b[2] = b[1]; bi[2] = bi[1];
            if (d < b[0]) { b[1] = b[0]; bi[1] = bi[0]; b[0] = d; bi[0] = c; }
            else          { b[1] = d;    bi[1] = c; }
        } else { b[2] = d; bi[2] = c; }
    }
}

// merge two sorted top-3 lists -> sorted top-3 (idx tiebreak: smaller wins)
__device__ __forceinline__ void merge3(float* av, int* ai,
                                       const float* bv, const int* bi) {
    float mv[3]; int mi[3];
    int pa = 0, pb = 0;
#pragma unroll
    for (int j = 0; j < 3; ++j) {
        bool takeA = (av[pa] < bv[pb]) || (av[pa] == bv[pb] && ai[pa] < bi[pb]);
        if (takeA) { mv[j] = av[pa]; mi[j] = ai[pa]; ++pa; }
        else       { mv[j] = bv[pb]; mi[j] = bi[pb]; ++pb; }
    }
#pragma unroll
    for (int j = 0; j < 3; ++j) { av[j] = mv[j]; ai[j] = mi[j]; }
}

// ---------------- prep: ||c||^2 + tf32-rounded codebook ----------------
__global__ __launch_bounds__(256) void prep_kernel(const float* __restrict__ cb) {
    int w = (blockIdx.x * blockDim.x + threadIdx.x) >> 5;
    int l = threadIdx.x & 31;
    if (w >= KCB) return;
    float4 v = ((const float4*)cb)[(size_t)w * 32 + l];
    float s = v.x * v.x + v.y * v.y + v.z * v.z + v.w * v.w;
    float4 tv;
    tv.x = tf32r(v.x); tv.y = tf32r(v.y); tv.z = tf32r(v.z); tv.w = tf32r(v.w);
    ((float4*)g_cb_tf)[(size_t)w * 32 + l] = tv;
#pragma unroll
    for (int o = 16; o; o >>= 1) s += __shfl_xor_sync(0xffffffffu, s, o);
    if (l == 0) g_cnorm[w] = s;
}

// ---------------- main: 1-pass tf32 screening, top-3 per token ----------------
__global__ __launch_bounds__(256, 1) void vq_kernel(
    const float* __restrict__ ze)
{
    extern __shared__ float sm[];
    float* As = sm;                  // tf32(-2*ze) [token][k], pad LDA
    float* Bs = sm + A_FLOATS;       // 2 stages of tf32 codebook chunk

    const int t      = threadIdx.x;
    const int lane   = t & 31;
    const int wid    = t >> 5;
    const int g      = lane >> 2;
    const int tg     = lane & 3;
    const int warp_m = wid >> 2;     // 0..1
    const int warp_n = wid & 3;      // 0..3

    const int tile  = blockIdx.x >> 2;
    const int q     = blockIdx.x & 3;
    const int tok0  = tile * TM;
    const int cbase = q * QCODES;

    // ---- load A = tf32(-2 * z_e) tile into smem ----
#pragma unroll
    for (int i = 0; i < 16; ++i) {
        int f   = t + i * 256;
        int row = f >> 5, k4 = f & 31;
        float4 v = ((const float4*)ze)[(size_t)(tok0 + row) * 32 + k4];
        v.x = tf32r(-2.f * v.x); v.y = tf32r(-2.f * v.y);
        v.z = tf32r(-2.f * v.z); v.w = tf32r(-2.f * v.w);
        *(float4*)&As[row * LDA + k4 * 4] = v;
    }

    // ---- prefetch chunk 0 (already tf32) ----
    {
        uint32_t bb = (uint32_t)__cvta_generic_to_shared(Bs);
#pragma unroll
        for (int i = 0; i < 16; ++i) {
            int f   = t + i * 256;
            int row = f >> 5, k4 = f & 31;
            cp_async16(bb + (uint32_t)(row * LDA + k4 * 4) * 4,
                       g_cb_tf + (size_t)(cbase + row) * DIMD + k4 * 4);
        }
        CP_COMMIT();
    }

    float best[8][3];
    int   bidx[8][3];
#pragma unroll
    for (int s = 0; s < 8; ++s)
#pragma unroll
        for (int j = 0; j < 3; ++j) { best[s][j] = 3.4e38f; bidx[s][j] = 0; }

    for (int ch = 0; ch < NCHUNK; ++ch) {
        if (ch + 1 < NCHUNK) {
            uint32_t bb = (uint32_t)__cvta_generic_to_shared(
                Bs + ((ch + 1) & 1) * B_FLOATS);
            const int code0 = cbase + (ch + 1) * CHUNK;
#pragma unroll
            for (int i = 0; i < 16; ++i) {
                int f   = t + i * 256;
                int row = f >> 5, k4 = f & 31;
                cp_async16(bb + (uint32_t)(row * LDA + k4 * 4) * 4,
                           g_cb_tf + (size_t)(code0 + row) * DIMD + k4 * 4);
            }
            CP_COMMIT();
            CP_WAIT1();
        } else {
            CP_WAIT0();
        }
        __syncthreads();

        const float* bs = Bs + (ch & 1) * B_FLOATS;

        float acc[4][4][4];
#pragma unroll
        for (int mt = 0; mt < 4; ++mt)
#pragma unroll
            for (int nt = 0; nt < 4; ++nt)
#pragma unroll
                for (int r = 0; r < 4; ++r) acc[mt][nt][r] = 0.f;

#pragma unroll 4
        for (int ks = 0; ks < 16; ++ks) {
            const int k0 = ks * 8;
            uint32_t af[4][4];
#pragma unroll
            for (int mt = 0; mt < 4; ++mt) {
                int r0 = warp_m * 64 + mt * 16 + g;
                af[mt][0] = __float_as_uint(As[r0 * LDA + k0 + tg]);
                af[mt][1] = __float_as_uint(As[(r0 + 8) * LDA + k0 + tg]);
                af[mt][2] = __float_as_uint(As[r0 * LDA + k0 + tg + 4]);
                af[mt][3] = __float_as_uint(As[(r0 + 8) * LDA + k0 + tg + 4]);
            }
            uint32_t bf[4][2];
#pragma unroll
            for (int nt = 0; nt < 4; ++nt) {
                int c0 = warp_n * 32 + nt * 8 + g;
                bf[nt][0] = __float_as_uint(bs[c0 * LDA + k0 + tg]);
                bf[nt][1] = __float_as_uint(bs[c0 * LDA + k0 + tg + 4]);
            }
#pragma unroll
            for (int mt = 0; mt < 4; ++mt)
#pragma unroll
                for (int nt = 0; nt < 4; ++nt)
                    mma_tf32(acc[mt][nt], af[mt], bf[nt]);
        }

        // ---- fold chunk into per-slot top-3 ----
        const int code0 = cbase + ch * CHUNK;
#pragma unroll
        for (int nt = 0; nt < 4; ++nt) {
            int cl = code0 + warp_n * 32 + nt * 8 + 2 * tg;
            float cn0 = __ldg(&g_cnorm[cl]);
            float cn1 = __ldg(&g_cnorm[cl + 1]);
#pragma unroll
            for (int mt = 0; mt < 4; ++mt) {
                int s0 = mt * 2, s1 = mt * 2 + 1;
                ins3(acc[mt][nt][0] + cn0, cl,     best[s0], bidx[s0]);
                ins3(acc[mt][nt][1] + cn1, cl + 1, best[s0], bidx[s0]);
                ins3(acc[mt][nt][2] + cn0, cl,     best[s1], bidx[s1]);
                ins3(acc[mt][nt][3] + cn1, cl + 1, best[s1], bidx[s1]);
            }
        }
        __syncthreads();
    }

    // ---- reduce top-3 across tg lanes (shfl), then across warp_n (smem) ----
#pragma unroll
    for (int s = 0; s < 8; ++s) {
#pragma unroll
        for (int off = 1; off < 4; off <<= 1) {
            float ov[3]; int oi[3];
#pragma unroll
            for (int j = 0; j < 3; ++j) {
                ov[j] = __shfl_xor_sync(0xffffffffu, best[s][j], off);
                oi[j] = __shfl_xor_sync(0xffffffffu, bidx[s][j], off);
            }
            merge3(best[s], bidx[s], ov, oi);
        }
    }
    __syncthreads();
    float* rv = sm;                       // [128][4][3]
    int*   ri = (int*)(sm + 128 * 12);    // [128][4][3]
#pragma unroll
    for (int s = 0; s < 8; ++s) {
        if (tg == 0) {
            int row = warp_m * 64 + (s >> 1) * 16 + g + 8 * (s & 1);
#pragma unroll
            for (int j = 0; j < 3; ++j) {
                rv[row * 12 + warp_n * 3 + j] = best[s][j];
                ri[row * 12 + warp_n * 3 + j] = bidx[s][j];
            }
        }
    }
    __syncthreads();
    if (t < TM) {
        float fv[3] = {rv[t * 12 + 0], rv[t * 12 + 1], rv[t * 12 + 2]};
        int   fi[3] = {ri[t * 12 + 0], ri[t * 12 + 1], ri[t * 12 + 2]};
#pragma unroll
        for (int w = 1; w < 4; ++w)
            merge3(fv, fi, &rv[t * 12 + w * 3], &ri[t * 12 + w * 3]);
        size_t base = ((size_t)q * TOKS + tok0 + t) * 3;
#pragma unroll
        for (int j = 0; j < 3; ++j) {
            g_bestd[base + j] = fv[j];
            g_besti[base + j] = fi[j];
        }
    }
}

// ---------------- merge quarters + margin rescore + gather ----------------
__global__ __launch_bounds__(256) void merge_gather_kernel(
    const float* __restrict__ ze, const float* __restrict__ cb,
    float* __restrict__ out, int out_size)
{
    __shared__ int sidx[64];
    const int t = threadIdx.x;
    const int tokBase = blockIdx.x * 64;

    if (t < 64) {
        int tok = tokBase + t;
        float cv[12]; int ci[12];
#pragma unroll
        for (int qq = 0; qq < NQ; ++qq) {
            size_t base = ((size_t)qq * TOKS + tok) * 3;
#pragma unroll
            for (int j = 0; j < 3; ++j) {
                cv[qq * 3 + j] = g_bestd[base + j];
                ci[qq * 3 + j] = g_besti[base + j];
            }
        }
        // global screened best (idx tiebreak)
        float b1v = cv[0]; int b1i = ci[0];
#pragma unroll
        for (int j = 1; j < 12; ++j)
            if (cv[j] < b1v || (cv[j] == b1v && ci[j] < b1i)) {
                b1v = cv[j]; b1i = ci[j];
            }
        // count window members
        int nwin = 0;
#pragma unroll
        for (int j = 0; j < 12; ++j)
            if (cv[j] <= b1v + TAU) ++nwin;

        int winner = b1i;
        if (nwin > 1) {
            // exact rescore of every in-window candidate (dedup by idx)
            const float* x = ze + (size_t)tok * DIMD;
            float bd = 3.4e38f; int bi = 0x7fffffff;
#pragma unroll 1
            for (int j = 0; j < 12; ++j) {
                if (cv[j] > b1v + TAU) continue;
                int c = ci[j];
                bool dup = false;
                for (int j2 = 0; j2 < j; ++j2)
                    if (cv[j2] <= b1v + TAU && ci[j2] == c) { dup = true; break; }
                if (dup) continue;
                const float4* cr = (const float4*)(cb + (size_t)c * DIMD);
                const float4* xr = (const float4*)x;
                float dot = 0.f;
#pragma unroll
                for (int k = 0; k < 32; ++k) {
                    float4 a = xr[k], b = cr[k];
                    dot = fmaf(a.x, b.x, dot);
                    dot = fmaf(a.y, b.y, dot);
                    dot = fmaf(a.z, b.z, dot);
                    dot = fmaf(a.w, b.w, dot);
                }
                float d2 = fmaf(-2.f, dot, __ldg(&g_cnorm[c]));
                if (d2 < bd || (d2 == bd && c < bi)) { bd = d2; bi = c; }
            }
            winner = bi;
        }
        sidx[t] = winner;
        if (out_size > TOKS * DIMD)
            out[(size_t)TOKS * DIMD + tok] = (float)winner;
    }
    __syncthreads();

    float4* outv = (float4*)out;
    const float4* cbv = (const float4*)cb;
#pragma unroll
    for (int i = 0; i < 8; ++i) {
        int f    = i * 256 + t;
        int tl   = f >> 5;
        int lanE = f & 31;
        outv[(size_t)(tokBase + tl) * 32 + lanE] =
            cbv[(size_t)sidx[tl] * 32 + lanE];
    }
}

extern "C" void kernel_launch(void* const* d_in, const int* in_sizes, int n_in,
                              void* d_out, int out_size) {
    const float* ze = (const float*)d_in[0];
    const float* cb = (const float*)d_in[1];
    if (n_in >= 2 && in_sizes[0] == KCB * DIMD && in_sizes[1] == TOKS * DIMD) {
        const float* tmp = ze; ze = cb; cb = tmp;
    }

    cudaFuncSetAttribute(vq_kernel, cudaFuncAttributeMaxDynamicSharedMemorySize,
                         SMEM_BYTES);

    prep_kernel<<<KCB / 8, 256>>>(cb);
    vq_kernel<<<NTILES * NQ, 256, SMEM_BYTES>>>(ze);
    merge_gather_kernel<<<TOKS / 64, 256>>>(ze, cb, (float*)d_out, out_size);
}

// round 6
// speedup vs baseline: 7.4573x; 4.2404x over previous
#include <cuda_runtime.h>
#include <cstdint>

// ---------------- problem constants ----------------
#define TOKS   32768
#define DIMD   128
#define KCB    8192
#define TM     128              // tokens per CTA
#define NQ     4                // codebook quarters
#define QCODES (KCB / NQ)       // 2048
#define CHUNK  128              // codes per B chunk
#define NCHUNK (QCODES / CHUNK) // 16
#define NTILES (TOKS / TM)      // 256
#define BIAS   512.0f
#define TAU    0.55f            // rescore window (includes quant slack)

#define A_BYTES      32768                  // packed A: 8 mb * 8 ks * 32 lanes * 16B
#define BSTAGE_BYTES 32768                  // packed B chunk: 16 nb * 4 ks2 * 32 * 16B
#define STG_FLOATS   (128 * 132)            // raw fp32 staging (padded rows)
#define SMEM_TOTAL   (A_BYTES + STG_FLOATS * 4)   // 100352

__device__ float g_cnorm[KCB];              // raw ||c||^2 (rescore)
__device__ float g_cnormb[KCB];             // ||c||^2 + BIAS (fold)
__device__ uint4 g_cb_pk[(KCB / 8) * 4 * 32];  // fragment-packed bf16 codebook (2MB)
__device__ float g_bestd[NQ * TOKS * 2];    // per-quarter screened top-2
__device__ int   g_besti[NQ * TOKS * 2];

// ---------------- PTX helpers (baseline sm_80+) ----------------
__device__ __forceinline__ uint32_t bf16x2(float hi, float lo) {
    uint32_t r;
    asm("cvt.rn.bf16x2.f32 %0, %1, %2;" : "=r"(r) : "f"(hi), "f"(lo));
    return r;  // low half = lo
}
__device__ __forceinline__ void cp_async16(uint32_t saddr, const void* gptr) {
    asm volatile("cp.async.cg.shared.global [%0], [%1], 16;"
                 :: "r"(saddr), "l"(gptr) : "memory");
}
#define CP_COMMIT() asm volatile("cp.async.commit_group;" ::: "memory")
#define CP_WAIT1()  asm volatile("cp.async.wait_group 1;" ::: "memory")
#define CP_WAIT0()  asm volatile("cp.async.wait_group 0;" ::: "memory")

__device__ __forceinline__ void mma_bf16(float* d, uint4 a,
                                         uint32_t b0, uint32_t b1) {
    asm volatile(
        "mma.sync.aligned.m16n8k16.row.col.f32.bf16.bf16.f32 "
        "{%0,%1,%2,%3}, {%4,%5,%6,%7}, {%8,%9}, {%0,%1,%2,%3};"
        : "+f"(d[0]), "+f"(d[1]), "+f"(d[2]), "+f"(d[3])
        : "r"(a.x), "r"(a.y), "r"(a.z), "r"(a.w), "r"(b0), "r"(b1));
}

// branchless top-2 (unsigned, smaller = better)
__device__ __forceinline__ void ins2(uint32_t& a, uint32_t& b, uint32_t u) {
    uint32_t mx = a > u ? a : u;
    a = a < u ? a : u;
    b = b < mx ? b : mx;
}
__device__ __forceinline__ bool cmpdc(float d1, int c1, float d2, int c2) {
    return d1 < d2 || (d1 == d2 && c1 < c2);
}
// merge two sorted-2 (d,c) lists into (a1,i1,a2,i2)
__device__ __forceinline__ void merge2(float& a1, int& i1, float& a2, int& i2,
                                       float b1, int j1, float b2, int j2) {
    bool t = cmpdc(a1, i1, b1, j1);
    float m1 = t ? a1 : b1;  int mi1 = t ? i1 : j1;
    float x1 = t ? b1 : a1;  int xi1 = t ? j1 : i1;   // loser's first
    float x2 = t ? a2 : b2;  int xi2 = t ? i2 : j2;   // winner's second
    bool t2 = cmpdc(x2, xi2, x1, xi1);
    a1 = m1; i1 = mi1;
    a2 = t2 ? x2 : x1; i2 = t2 ? xi2 : xi1;
}

// ---------------- prep 1: code norms ----------------
__global__ __launch_bounds__(256) void prep_norm_kernel(const float* __restrict__ cb) {
    int w = (blockIdx.x * blockDim.x + threadIdx.x) >> 5;
    int l = threadIdx.x & 31;
    if (w >= KCB) return;
    float4 v = ((const float4*)cb)[(size_t)w * 32 + l];
    float s = v.x * v.x + v.y * v.y + v.z * v.z + v.w * v.w;
#pragma unroll
    for (int o = 16; o; o >>= 1) s += __shfl_xor_sync(0xffffffffu, s, o);
    if (l == 0) { g_cnorm[w] = s; g_cnormb[w] = s + BIAS; }
}

// ---------------- prep 2: fragment-packed bf16 codebook ----------------
// warp per 8-code block nb; lane (g,tg) writes uint4 per ks2:
// {k0+2tg..+1, k0+8+2tg..+1, k0+16+2tg..+1, k0+24+2tg..+1} of code nb*8+g
__global__ __launch_bounds__(256) void prep_pack_kernel(const float* __restrict__ cb) {
    int nb = (blockIdx.x * blockDim.x + threadIdx.x) >> 5;
    int lane = threadIdx.x & 31;
    if (nb >= KCB / 8) return;
    int g = lane >> 2, tg = lane & 3;
    const float* row = cb + (size_t)(nb * 8 + g) * DIMD;
#pragma unroll
    for (int ks2 = 0; ks2 < 4; ++ks2) {
        int k0 = ks2 * 32;
        float2 a = *(const float2*)&row[k0 + 2 * tg];
        float2 b = *(const float2*)&row[k0 + 8 + 2 * tg];
        float2 c = *(const float2*)&row[k0 + 16 + 2 * tg];
        float2 d = *(const float2*)&row[k0 + 24 + 2 * tg];
        uint4 u;
        u.x = bf16x2(a.y, a.x); u.y = bf16x2(b.y, b.x);
        u.z = bf16x2(c.y, c.x); u.w = bf16x2(d.y, d.x);
        g_cb_pk[((size_t)nb * 4 + ks2) * 32 + lane] = u;
    }
}

// ---------------- main VQ kernel: bf16 screening, packed-uint top-2 ----------------
__global__ __launch_bounds__(256, 2) void vq_kernel(const float* __restrict__ ze)
{
    extern __shared__ char smem[];
    uint4* Apk = (uint4*)smem;                       // [mb][ks][lane]
    float* stg = (float*)(smem + A_BYTES);           // raw fp32 staging (aliased w/ B)

    const int t      = threadIdx.x;
    const int lane   = t & 31;
    const int wid    = t >> 5;
    const int g      = lane >> 2;
    const int tg     = lane & 3;
    const int warp_m = wid >> 2;     // 0..1
    const int warp_n = wid & 3;      // 0..3

    const int tile  = blockIdx.x >> 2;
    const int q     = blockIdx.x & 3;
    const int tok0  = tile * TM;
    const int cbase = q * QCODES;

    // ---- stage raw ze tile (coalesced cp.async) ----
    {
        uint32_t sb = (uint32_t)__cvta_generic_to_shared(stg);
#pragma unroll
        for (int i = 0; i < 16; ++i) {
            int f = t + i * 256;
            int r = f >> 5, c4 = f & 31;
            cp_async16(sb + (uint32_t)(r * 132 + c4 * 4) * 4,
                       ze + (size_t)(tok0 + r) * DIMD + c4 * 4);
        }
        CP_COMMIT(); CP_WAIT0();
    }
    __syncthreads();

    // ---- pack A = bf16(-2*ze) into fragment order: warp wid handles mb=wid ----
    {
        const int mb = wid;
        const int r0 = mb * 16 + g, r1 = r0 + 8;
#pragma unroll
        for (int ks = 0; ks < 8; ++ks) {
            int c0 = ks * 16 + 2 * tg, c1 = c0 + 8;
            float2 v00 = *(const float2*)&stg[r0 * 132 + c0];
            float2 v10 = *(const float2*)&stg[r1 * 132 + c0];
            float2 v01 = *(const float2*)&stg[r0 * 132 + c1];
            float2 v11 = *(const float2*)&stg[r1 * 132 + c1];
            uint4 u;
            u.x = bf16x2(-2.f * v00.y, -2.f * v00.x);
            u.y = bf16x2(-2.f * v10.y, -2.f * v10.x);
            u.z = bf16x2(-2.f * v01.y, -2.f * v01.x);
            u.w = bf16x2(-2.f * v11.y, -2.f * v11.x);
            Apk[(mb * 8 + ks) * 32 + lane] = u;
        }
    }
    __syncthreads();   // staging consumed; B stages may now overwrite it

    // ---- prefetch B chunk 0 (contiguous packed 32KB) ----
    {
        uint32_t bb = (uint32_t)__cvta_generic_to_shared(smem + A_BYTES);
        const char* src = (const char*)&g_cb_pk[((size_t)(cbase) >> 3) * 4 * 32];
#pragma unroll
        for (int i = 0; i < 8; ++i)
            cp_async16(bb + (uint32_t)(i * 256 + t) * 16, src + (i * 256 + t) * 16);
        CP_COMMIT();
    }

    uint32_t top1[8], top2v[8];
#pragma unroll
    for (int s = 0; s < 8; ++s) { top1[s] = 0xFFFFFFFFu; top2v[s] = 0xFFFFFFFFu; }

    const uint32_t MASK = 0xFFFFFF80u;

    for (int ch = 0; ch < NCHUNK; ++ch) {
        if (ch + 1 < NCHUNK) {
            uint32_t bb = (uint32_t)__cvta_generic_to_shared(
                smem + A_BYTES + ((ch + 1) & 1) * BSTAGE_BYTES);
            const char* src = (const char*)
                &g_cb_pk[((size_t)(cbase + (ch + 1) * CHUNK) >> 3) * 4 * 32];
#pragma unroll
            for (int i = 0; i < 8; ++i)
                cp_async16(bb + (uint32_t)(i * 256 + t) * 16,
                           src + (i * 256 + t) * 16);
            CP_COMMIT(); CP_WAIT1();
        } else {
            CP_WAIT0();
        }
        __syncthreads();

        const uint4* bs = (const uint4*)(smem + A_BYTES + (ch & 1) * BSTAGE_BYTES);

        float acc[4][4][4];
#pragma unroll
        for (int mt = 0; mt < 4; ++mt)
#pragma unroll
            for (int nt = 0; nt < 4; ++nt)
#pragma unroll
                for (int r = 0; r < 4; ++r) acc[mt][nt][r] = 0.f;

#pragma unroll
        for (int ks2 = 0; ks2 < 4; ++ks2) {
            uint4 B4[4];
#pragma unroll
            for (int nt = 0; nt < 4; ++nt)
                B4[nt] = bs[(((warp_n * 4 + nt) * 4) + ks2) * 32 + lane];
            uint4 A4[4];
#pragma unroll
            for (int mt = 0; mt < 4; ++mt)
                A4[mt] = Apk[((warp_m * 4 + mt) * 8 + 2 * ks2) * 32 + lane];
#pragma unroll
            for (int mt = 0; mt < 4; ++mt)
#pragma unroll
                for (int nt = 0; nt < 4; ++nt)
                    mma_bf16(acc[mt][nt], A4[mt], B4[nt].x, B4[nt].y);
#pragma unroll
            for (int mt = 0; mt < 4; ++mt)
                A4[mt] = Apk[((warp_m * 4 + mt) * 8 + 2 * ks2 + 1) * 32 + lane];
#pragma unroll
            for (int mt = 0; mt < 4; ++mt)
#pragma unroll
                for (int nt = 0; nt < 4; ++nt)
                    mma_bf16(acc[mt][nt], A4[mt], B4[nt].z, B4[nt].w);
        }

        // ---- branchless fold: pack (d2+BIAS, 7-bit local id) into uint ----
#pragma unroll
        for (int nt = 0; nt < 4; ++nt) {
            int cg = cbase + ch * CHUNK + warp_n * 32 + nt * 8 + 2 * tg;
            float cn0 = __ldg(&g_cnormb[cg]);
            float cn1 = __ldg(&g_cnormb[cg + 1]);
            uint32_t lidb = (uint32_t)(ch * 8 + nt * 2);
#pragma unroll
            for (int mt = 0; mt < 4; ++mt) {
                int s0 = mt * 2, s1 = s0 + 1;
                uint32_t u;
                u = (__float_as_uint(acc[mt][nt][0] + cn0) & MASK) | lidb;
                ins2(top1[s0], top2v[s0], u);
                u = (__float_as_uint(acc[mt][nt][1] + cn1) & MASK) | (lidb + 1);
                ins2(top1[s0], top2v[s0], u);
                u = (__float_as_uint(acc[mt][nt][2] + cn0) & MASK) | lidb;
                ins2(top1[s1], top2v[s1], u);
                u = (__float_as_uint(acc[mt][nt][3] + cn1) & MASK) | (lidb + 1);
                ins2(top1[s1], top2v[s1], u);
            }
        }
        __syncthreads();   // all reads of this B stage done before overwrite
    }

    // ---- decode + reduce across tg (shfl) and warp_n (smem) ----
    float* rv = (float*)smem;                 // [128][4][2]
    int*   ri = (int*)(smem + 4096);          // [128][4][2]

#pragma unroll
    for (int s = 0; s < 8; ++s) {
        // decode slot top-2 to (float d, int code)
        float d1 = __uint_as_float(top1[s] & MASK);
        float d2 = __uint_as_float(top2v[s] & MASK);
        int l1 = (int)(top1[s] & 127u), l2 = (int)(top2v[s] & 127u);
        int c1 = cbase + (l1 >> 3) * CHUNK + warp_n * 32 + ((l1 >> 1) & 3) * 8
               + 2 * tg + (l1 & 1);
        int c2 = cbase + (l2 >> 3) * CHUNK + warp_n * 32 + ((l2 >> 1) & 3) * 8
               + 2 * tg + (l2 & 1);
#pragma unroll
        for (int off = 1; off < 4; off <<= 1) {
            float od1 = __shfl_xor_sync(0xffffffffu, d1, off);
            float od2 = __shfl_xor_sync(0xffffffffu, d2, off);
            int   oc1 = __shfl_xor_sync(0xffffffffu, c1, off);
            int   oc2 = __shfl_xor_sync(0xffffffffu, c2, off);
            merge2(d1, c1, d2, c2, od1, oc1, od2, oc2);
        }
        if (tg == 0) {
            int mt = s >> 1, half = s & 1;
            int row = warp_m * 64 + mt * 16 + g + half * 8;
            rv[row * 8 + warp_n * 2 + 0] = d1;
            rv[row * 8 + warp_n * 2 + 1] = d2;
            ri[row * 8 + warp_n * 2 + 0] = c1;
            ri[row * 8 + warp_n * 2 + 1] = c2;
        }
    }
    __syncthreads();

    if (t < TM) {
        float d1 = rv[t * 8 + 0], d2 = rv[t * 8 + 1];
        int   c1 = ri[t * 8 + 0], c2 = ri[t * 8 + 1];
#pragma unroll
        for (int w = 1; w < 4; ++w)
            merge2(d1, c1, d2, c2,
                   rv[t * 8 + w * 2], ri[t * 8 + w * 2],
                   rv[t * 8 + w * 2 + 1], ri[t * 8 + w * 2 + 1]);
        size_t base = ((size_t)q * TOKS + tok0 + t) * 2;
        g_bestd[base + 0] = d1; g_bestd[base + 1] = d2;
        g_besti[base + 0] = c1; g_besti[base + 1] = c2;
    }
}

// ---------------- merge quarters + exact rescore + gather ----------------
__global__ __launch_bounds__(256) void merge_gather_kernel(
    const float* __restrict__ ze, const float* __restrict__ cb,
    float* __restrict__ out, int out_size)
{
    __shared__ int sidx[64];
    const int t = threadIdx.x;
    const int tokBase = blockIdx.x * 64;

    if (t < 64) {
        int tok = tokBase + t;
        float cv[8]; int ci[8];
#pragma unroll
        for (int qq = 0; qq < NQ; ++qq) {
            size_t base = ((size_t)qq * TOKS + tok) * 2;
            cv[qq * 2 + 0] = g_bestd[base + 0]; ci[qq * 2 + 0] = g_besti[base + 0];
            cv[qq * 2 + 1] = g_bestd[base + 1]; ci[qq * 2 + 1] = g_besti[base + 1];
        }
        float b1v = cv[0]; int b1i = ci[0];
#pragma unroll
        for (int j = 1; j < 8; ++j)
            if (cmpdc(cv[j], ci[j], b1v, b1i)) { b1v = cv[j]; b1i = ci[j]; }
        int nwin = 0;
#pragma unroll
        for (int j = 0; j < 8; ++j)
            if (cv[j] <= b1v + TAU) ++nwin;

        int winner = b1i;
        if (nwin > 1) {
            const float4* xr = (const float4*)(ze + (size_t)tok * DIMD);
            float bd = 3.4e38f; int bi = 0x7fffffff;
#pragma unroll 1
            for (int j = 0; j < 8; ++j) {
                if (cv[j] > b1v + TAU) continue;
                int c = ci[j];
                const float4* cr = (const float4*)(cb + (size_t)c * DIMD);
                float dot = 0.f;
#pragma unroll
                for (int k = 0; k < 32; ++k) {
                    float4 a = xr[k], b = cr[k];
                    dot = fmaf(a.x, b.x, dot);
                    dot = fmaf(a.y, b.y, dot);
                    dot = fmaf(a.z, b.z, dot);
                    dot = fmaf(a.w, b.w, dot);
                }
                float d2 = fmaf(-2.f, dot, __ldg(&g_cnorm[c]));
                if (d2 < bd || (d2 == bd && c < bi)) { bd = d2; bi = c; }
            }
            winner = bi;
        }
        sidx[t] = winner;
        if (out_size > TOKS * DIMD)
            out[(size_t)TOKS * DIMD + tok] = (float)winner;
    }
    __syncthreads();

    float4* outv = (float4*)out;
    const float4* cbv = (const float4*)cb;
#pragma unroll
    for (int i = 0; i < 8; ++i) {
        int f  = i * 256 + t;
        int tl = f >> 5;
        int k4 = f & 31;
        outv[(size_t)(tokBase + tl) * 32 + k4] = cbv[(size_t)sidx[tl] * 32 + k4];
    }
}

extern "C" void kernel_launch(void* const* d_in, const int* in_sizes, int n_in,
                              void* d_out, int out_size) {
    const float* ze = (const float*)d_in[0];
    const float* cb = (const float*)d_in[1];
    if (n_in >= 2 && in_sizes[0] == KCB * DIMD && in_sizes[1] == TOKS * DIMD) {
        const float* tmp = ze; ze = cb; cb = tmp;
    }

    cudaFuncSetAttribute(vq_kernel, cudaFuncAttributeMaxDynamicSharedMemorySize,
                         SMEM_TOTAL);

    prep_norm_kernel<<<KCB * 32 / 256, 256>>>(cb);
    prep_pack_kernel<<<(KCB / 8) * 32 / 256, 256>>>(cb);
    vq_kernel<<<NTILES * NQ, 256, SMEM_TOTAL>>>(ze);
    merge_gather_kernel<<<TOKS / 64, 256>>>(ze, cb, (float*)d_out, out_size);
}